// round 17
// baseline (speedup 1.0000x reference)
#include <cuda_runtime.h>
#include <cuda_fp16.h>
#include <cstdint>

// Problem constants
#define D_MODEL 768
#define D_INNER 768
#define D_STATE 8
#define BATCH   4
#define SEQ     8192
#define M_TOT   (BATCH * SEQ)        // 32768
#define N_IN    (2 * D_INNER)        // 1536
#define KDIM    768
#define CHUNK   32
#define NCHUNK  (SEQ / CHUNK)        // 256
#define NVBLK   (BATCH * NCHUNK)     // 1024

// Scratch (static __device__ arrays per allocation rules)
__device__ __half g_Xh[(size_t)M_TOT * D_MODEL];         // fp16 x
__device__ __half g_XC[(size_t)M_TOT * D_INNER];         // xc fp16 (pre-conv)
__device__ __half g_ZS[(size_t)M_TOT * D_INNER];         // silu(z) fp16
__device__ __half g_YZh[(size_t)M_TOT * D_INNER];        // fp16 y*silu(z)
__device__ __half g_Wh[(size_t)KDIM * N_IN + (size_t)KDIM * D_MODEL]; // fp16 W_in | W_out
__device__ float  g_AG[(size_t)NVBLK * D_INNER];         // chunk aggregates
__device__ float  g_PR[(size_t)NVBLK * D_INNER];         // inclusive prefixes
__device__ int    g_ST[NVBLK];                           // status: 0/1(agg)/2(prefix)
__device__ int    g_TK[1];                               // ticket counter

// ---------------------------------------------------------------------------
// silu helper
// ---------------------------------------------------------------------------
__device__ __forceinline__ float silu_f(float v) {
    return v / (1.0f + __expf(-v));
}

// ---------------------------------------------------------------------------
// fp32 -> fp16 conversion (used for x and both weights)
// ---------------------------------------------------------------------------
__global__ __launch_bounds__(256) void convert_h_kernel(
    const float* __restrict__ in, __half* __restrict__ out, int n4)
{
    int i = blockIdx.x * blockDim.x + threadIdx.x;
    if (i >= n4) return;
    float4 v = ((const float4*)in)[i];
    __half2 h0 = __floats2half2_rn(v.x, v.y);
    __half2 h1 = __floats2half2_rn(v.z, v.w);
    ((uint2*)out)[i] = make_uint2(*(uint32_t*)&h0, *(uint32_t*)&h1);
}

// ---------------------------------------------------------------------------
// FP16 tensor-core GEMM (unchanged from R16 best): 128x128, BK=32, 3-stage,
// ldmatrix, 8 warps 32x64 warptiles, m16n8k16 fp32-acc.
// ---------------------------------------------------------------------------
#define BM 128
#define BN 128
#define BKT 32
#define STAGES 3
#define AH_STRIDE 40
#define BH_STRIDE 136
#define A_STAGE_H (BM * AH_STRIDE)
#define B_STAGE_H (BKT * BH_STRIDE)
#define GEMM_SMEM_BYTES (STAGES * (A_STAGE_H + B_STAGE_H) * 2)  // 56832

__device__ __forceinline__ void mma_fp16(float* d, const uint32_t* a, const uint32_t* b) {
    asm volatile(
        "mma.sync.aligned.m16n8k16.row.col.f32.f16.f16.f32 "
        "{%0,%1,%2,%3}, {%4,%5,%6,%7}, {%8,%9}, {%0,%1,%2,%3};\n"
        : "+f"(d[0]), "+f"(d[1]), "+f"(d[2]), "+f"(d[3])
        : "r"(a[0]), "r"(a[1]), "r"(a[2]), "r"(a[3]), "r"(b[0]), "r"(b[1]));
}

__device__ __forceinline__ void ldsm_x4(uint32_t* r, uint32_t addr) {
    asm volatile("ldmatrix.sync.aligned.m8n8.x4.shared.b16 {%0,%1,%2,%3}, [%4];"
                 : "=r"(r[0]), "=r"(r[1]), "=r"(r[2]), "=r"(r[3]) : "r"(addr));
}
__device__ __forceinline__ void ldsm_x4_t(uint32_t* r, uint32_t addr) {
    asm volatile("ldmatrix.sync.aligned.m8n8.x4.trans.shared.b16 {%0,%1,%2,%3}, [%4];"
                 : "=r"(r[0]), "=r"(r[1]), "=r"(r[2]), "=r"(r[3]) : "r"(addr));
}

__device__ __forceinline__ void cpa16(void* dst, const void* src) {
    unsigned d = (unsigned)__cvta_generic_to_shared(dst);
    asm volatile("cp.async.cg.shared.global [%0], [%1], 16;" :: "r"(d), "l"(src) : "memory");
}

template<bool SPLIT>
__global__ __launch_bounds__(256, 2) void gemm_fp16_kernel(
    const __half* __restrict__ A, const __half* __restrict__ Bh,
    float* __restrict__ Cf, __half* __restrict__ Cxc, __half* __restrict__ Czs,
    int M, int N, int K)
{
    extern __shared__ char smem[];
    __half* Asm = (__half*)smem;
    __half* Bsm = (__half*)(smem + STAGES * A_STAGE_H * 2);

    const int tid  = threadIdx.x;
    const int lane = tid & 31;
    const int wid  = tid >> 5;
    const int wm   = wid >> 1;
    const int wn   = wid & 1;
    const int bm   = blockIdx.y;
    const int bn   = blockIdx.x;

    const __half* Ab = A + (size_t)bm * BM * K;
    const __half* Bb = Bh + (size_t)bn * BN;

    float acc[2][8][4];
    #pragma unroll
    for (int mi = 0; mi < 2; mi++)
        #pragma unroll
        for (int ni = 0; ni < 8; ni++)
            #pragma unroll
            for (int q = 0; q < 4; q++) acc[mi][ni][q] = 0.0f;

    const int NT = K / BKT;

    auto load_stage = [&](int kt, int st) {
        __half* As = Asm + st * A_STAGE_H;
        __half* Bs = Bsm + st * B_STAGE_H;
        const int k0 = kt * BKT;
        #pragma unroll
        for (int i = 0; i < 2; i++) {
            const int idx = tid + i * 256;
            const int r = idx >> 2, c8 = (idx & 3) << 3;
            cpa16(&As[r * AH_STRIDE + c8], Ab + (size_t)r * K + k0 + c8);
        }
        #pragma unroll
        for (int i = 0; i < 2; i++) {
            const int idx = tid + i * 256;
            const int r = idx >> 4, c8 = (idx & 15) << 3;
            cpa16(&Bs[r * BH_STRIDE + c8], Bb + (size_t)(k0 + r) * N + c8);
        }
        asm volatile("cp.async.commit_group;" ::: "memory");
    };

    const uint32_t asm_u32 = (uint32_t)__cvta_generic_to_shared(Asm);
    const uint32_t bsm_u32 = (uint32_t)__cvta_generic_to_shared(Bsm);
    const uint32_t a_lane = ((wm * 32 + (lane & 15)) * AH_STRIDE + (lane >> 4) * 8) * 2;
    const uint32_t b_lane = (((((lane >> 3) & 1) * 8) + (lane & 7)) * BH_STRIDE
                             + wn * 64 + (lane >> 4) * 8) * 2;

    load_stage(0, 0);
    load_stage(1, 1);

    for (int kt = 0; kt < NT; kt++) {
        if (kt + 2 < NT) {
            asm volatile("cp.async.wait_group 1;" ::: "memory");
        } else {
            asm volatile("cp.async.wait_group 0;" ::: "memory");
        }
        __syncthreads();

        if (kt + 2 < NT) load_stage(kt + 2, (kt + 2) % STAGES);

        const int st = kt % STAGES;
        const uint32_t a_st = asm_u32 + st * A_STAGE_H * 2 + a_lane;
        const uint32_t b_st = bsm_u32 + st * B_STAGE_H * 2 + b_lane;

        #pragma unroll
        for (int ks2 = 0; ks2 < 2; ks2++) {
            uint32_t afr[2][4];
            const uint32_t aa = a_st + ks2 * 32;
            ldsm_x4(afr[0], aa);
            ldsm_x4(afr[1], aa + 16 * AH_STRIDE * 2);

            uint32_t bfr[8][2];
            #pragma unroll
            for (int ni2 = 0; ni2 < 4; ni2++) {
                uint32_t r[4];
                ldsm_x4_t(r, b_st + ks2 * 16 * BH_STRIDE * 2 + ni2 * 32);
                bfr[2 * ni2][0] = r[0]; bfr[2 * ni2][1] = r[1];
                bfr[2 * ni2 + 1][0] = r[2]; bfr[2 * ni2 + 1][1] = r[3];
            }
            #pragma unroll
            for (int mi = 0; mi < 2; mi++)
                #pragma unroll
                for (int ni = 0; ni < 8; ni++)
                    mma_fp16(acc[mi][ni], afr[mi], bfr[ni]);
        }
    }

    if (!SPLIT) {
        float* Cb = Cf + (size_t)bm * BM * N + (size_t)bn * BN;
        #pragma unroll
        for (int mi = 0; mi < 2; mi++) {
            #pragma unroll
            for (int ni = 0; ni < 8; ni++) {
                const int r = wm * 32 + mi * 16 + (lane >> 2);
                const int c = wn * 64 + ni * 8 + ((lane & 3) << 1);
                *(float2*)&Cb[(size_t)r * N + c] =
                    make_float2(acc[mi][ni][0], acc[mi][ni][1]);
                *(float2*)&Cb[(size_t)(r + 8) * N + c] =
                    make_float2(acc[mi][ni][2], acc[mi][ni][3]);
            }
        }
    } else if (bn < 6) {
        __half* Xb = Cxc + (size_t)bm * BM * D_INNER + (size_t)bn * BN;
        #pragma unroll
        for (int mi = 0; mi < 2; mi++) {
            #pragma unroll
            for (int ni = 0; ni < 8; ni++) {
                const int r = wm * 32 + mi * 16 + (lane >> 2);
                const int c = wn * 64 + ni * 8 + ((lane & 3) << 1);
                __half2 h0 = __floats2half2_rn(acc[mi][ni][0], acc[mi][ni][1]);
                __half2 h1 = __floats2half2_rn(acc[mi][ni][2], acc[mi][ni][3]);
                *(uint32_t*)&Xb[(size_t)r * D_INNER + c] = *(uint32_t*)&h0;
                *(uint32_t*)&Xb[(size_t)(r + 8) * D_INNER + c] = *(uint32_t*)&h1;
            }
        }
    } else {
        __half* Zb = Czs + (size_t)bm * BM * D_INNER + (size_t)(bn - 6) * BN;
        #pragma unroll
        for (int mi = 0; mi < 2; mi++) {
            #pragma unroll
            for (int ni = 0; ni < 8; ni++) {
                const int r = wm * 32 + mi * 16 + (lane >> 2);
                const int c = wn * 64 + ni * 8 + ((lane & 3) << 1);
                __half2 h0 = __floats2half2_rn(silu_f(acc[mi][ni][0]),
                                               silu_f(acc[mi][ni][1]));
                __half2 h1 = __floats2half2_rn(silu_f(acc[mi][ni][2]),
                                               silu_f(acc[mi][ni][3]));
                *(uint32_t*)&Zb[(size_t)r * D_INNER + c] = *(uint32_t*)&h0;
                *(uint32_t*)&Zb[(size_t)(r + 8) * D_INNER + c] = *(uint32_t*)&h1;
            }
        }
    }
}

// ---------------------------------------------------------------------------
// fp16 quad load helper
// ---------------------------------------------------------------------------
__device__ __forceinline__ void ld_h4(const __half* p, float* f) {
    uint2 raw = *(const uint2*)p;
    float2 a = __half22float2(*(__half2*)&raw.x);
    float2 b = __half22float2(*(__half2*)&raw.y);
    f[0] = a.x; f[1] = a.y; f[2] = b.x; f[3] = b.y;
}

// ---------------------------------------------------------------------------
// Init: reset status + ticket (per graph replay)
// ---------------------------------------------------------------------------
__global__ __launch_bounds__(256) void scan_init_kernel(int* status, int* ticket)
{
    int i = blockIdx.x * blockDim.x + threadIdx.x;
    if (i < NVBLK) status[i] = 0;
    if (i == 0) *ticket = 0;
}

// ---------------------------------------------------------------------------
// Fused single-pass scan with decoupled lookback.
// Block = 192 threads (4 channels each), ticket -> (batch, chunk).
// Phase 1: chunk sum of u=silu(conv3(xc)+b)  -> agg, status=1
// Phase 2: lookback exclusive prefix          -> pref, status=2
// Phase 3: re-run conv (xc L1-hot) + apply    -> yz fp16
// ---------------------------------------------------------------------------
__global__ __launch_bounds__(192) void scan_fused_kernel(
    const __half* __restrict__ xc, const __half* __restrict__ zs,
    const float* __restrict__ convw, const float* __restrict__ convb,
    const float* __restrict__ Bm, const float* __restrict__ Cm,
    const float* __restrict__ Dv,
    float* __restrict__ agg, float* __restrict__ pref,
    int* __restrict__ status, int* __restrict__ ticket,
    __half* __restrict__ yz)
{
    __shared__ int s_vid;
    __shared__ int s_st;
    const int tq = threadIdx.x;
    if (tq == 0) s_vid = atomicAdd(ticket, 1);
    __syncthreads();
    const int v = s_vid;
    const int b = v >> 8;          // NCHUNK = 256
    const int chunk = v & (NCHUNK - 1);
    const int t0 = chunk * CHUNK;
    const int c0 = tq * 4;

    float w0[4], w1[4], w2[4], cb[4], bc[4], dd[4];
    #pragma unroll
    for (int j = 0; j < 4; j++) {
        w0[j] = convw[(c0 + j) * 3 + 0];
        w1[j] = convw[(c0 + j) * 3 + 1];
        w2[j] = convw[(c0 + j) * 3 + 2];
        cb[j] = convb[c0 + j];
        float acc = 0.0f;
        #pragma unroll
        for (int s = 0; s < D_STATE; s++)
            acc = fmaf(Bm[(c0 + j) * D_STATE + s], Cm[(c0 + j) * D_STATE + s], acc);
        bc[j] = acc;
        dd[j] = Dv[c0 + j];
    }

    const __half* p  = xc + ((size_t)b * SEQ + t0) * D_INNER + c0;
    const __half* zp = zs + ((size_t)b * SEQ + t0) * D_INNER + c0;
    __half* q = yz + ((size_t)b * SEQ + t0) * D_INNER + c0;

    float m2i[4] = {0, 0, 0, 0}, m1i[4] = {0, 0, 0, 0};
    if (t0 >= 2) {
        ld_h4(p - 2 * D_INNER, m2i);
        ld_h4(p - 1 * D_INNER, m1i);
    }

    // Phase 1: chunk sum
    float s[4] = {0, 0, 0, 0};
    {
        float m2[4], m1[4];
        #pragma unroll
        for (int j = 0; j < 4; j++) { m2[j] = m2i[j]; m1[j] = m1i[j]; }
        #pragma unroll 8
        for (int t = 0; t < CHUNK; t++) {
            float cc[4];
            ld_h4(p + (size_t)t * D_INNER, cc);
            #pragma unroll
            for (int j = 0; j < 4; j++) {
                float vv = fmaf(w0[j], m2[j], fmaf(w1[j], m1[j], fmaf(w2[j], cc[j], cb[j])));
                s[j] += silu_f(vv);
                m2[j] = m1[j]; m1[j] = cc[j];
            }
        }
    }
    const size_t vbase = (size_t)v * D_INNER + c0;
    *(float4*)&agg[vbase] = make_float4(s[0], s[1], s[2], s[3]);
    __threadfence();
    __syncthreads();
    if (tq == 0) atomicExch(&status[v], 1);

    // Phase 2: lookback for exclusive prefix
    float run[4] = {0, 0, 0, 0};
    for (int j = chunk - 1; j >= 0; ) {
        if (tq == 0) {
            int st;
            do { st = *(volatile int*)&status[(b << 8) + j]; } while (st == 0);
            s_st = st;
        }
        __syncthreads();
        const int st = s_st;
        __threadfence();  // order status read before data read
        const float* src = (st == 2 ? pref : agg);
        float4 vv = *(const float4*)&src[((size_t)((b << 8) + j)) * D_INNER + c0];
        run[0] += vv.x; run[1] += vv.y; run[2] += vv.z; run[3] += vv.w;
        __syncthreads();  // protect s_st before next iteration overwrite
        if (st == 2) break;
        j--;
    }

    // Publish inclusive prefix
    *(float4*)&pref[vbase] =
        make_float4(run[0] + s[0], run[1] + s[1], run[2] + s[2], run[3] + s[3]);
    __threadfence();
    __syncthreads();
    if (tq == 0) atomicExch(&status[v], 2);

    // Phase 3: apply (xc slice is L1-hot from phase 1)
    {
        float m2[4], m1[4];
        #pragma unroll
        for (int j = 0; j < 4; j++) { m2[j] = m2i[j]; m1[j] = m1i[j]; }
        #pragma unroll 8
        for (int t = 0; t < CHUNK; t++) {
            float cc[4], zv[4];
            ld_h4(p + (size_t)t * D_INNER, cc);
            ld_h4(zp + (size_t)t * D_INNER, zv);
            float o[4];
            #pragma unroll
            for (int j = 0; j < 4; j++) {
                float vv = fmaf(w0[j], m2[j], fmaf(w1[j], m1[j], fmaf(w2[j], cc[j], cb[j])));
                float u = silu_f(vv);
                run[j] += u;
                float y = fmaf(run[j], bc[j], u * dd[j]);
                o[j] = y * zv[j];
                m2[j] = m1[j]; m1[j] = cc[j];
            }
            __half2 h01 = __floats2half2_rn(o[0], o[1]);
            __half2 h23 = __floats2half2_rn(o[2], o[3]);
            *(uint2*)(q + (size_t)t * D_INNER) =
                make_uint2(*(uint32_t*)&h01, *(uint32_t*)&h23);
        }
    }
}

// ---------------------------------------------------------------------------
// Launch
// ---------------------------------------------------------------------------
extern "C" void kernel_launch(void* const* d_in, const int* in_sizes, int n_in,
                              void* d_out, int out_size)
{
    const float* x      = (const float*)d_in[0];
    const float* W_in   = (const float*)d_in[1];
    const float* conv_w = (const float*)d_in[2];
    const float* conv_b = (const float*)d_in[3];
    const float* Bm     = (const float*)d_in[4];
    const float* Cm     = (const float*)d_in[5];
    const float* Dv     = (const float*)d_in[6];
    const float* W_out  = (const float*)d_in[7];
    float* out = (float*)d_out;

    __half* xh;  cudaGetSymbolAddress((void**)&xh, g_Xh);
    __half* xcp; cudaGetSymbolAddress((void**)&xcp, g_XC);
    __half* zsp; cudaGetSymbolAddress((void**)&zsp, g_ZS);
    __half* yzh; cudaGetSymbolAddress((void**)&yzh, g_YZh);
    __half* wh;  cudaGetSymbolAddress((void**)&wh, g_Wh);
    float*  ag;  cudaGetSymbolAddress((void**)&ag, g_AG);
    float*  pr;  cudaGetSymbolAddress((void**)&pr, g_PR);
    int*    st;  cudaGetSymbolAddress((void**)&st, g_ST);
    int*    tk;  cudaGetSymbolAddress((void**)&tk, g_TK);

    __half* wh_in  = wh;                             // [768][1536]
    __half* wh_out = wh + (size_t)KDIM * N_IN;       // [768][768]

    static bool attr_done = false;
    if (!attr_done) {
        cudaFuncSetAttribute(gemm_fp16_kernel<true>,
                             cudaFuncAttributeMaxDynamicSharedMemorySize, GEMM_SMEM_BYTES);
        cudaFuncSetAttribute(gemm_fp16_kernel<false>,
                             cudaFuncAttributeMaxDynamicSharedMemorySize, GEMM_SMEM_BYTES);
        attr_done = true;
    }

    // Reset scan state (every replay) + preprocessing converts
    scan_init_kernel<<<4, 256>>>(st, tk);
    {
        int n4 = (M_TOT * D_MODEL) / 4;
        convert_h_kernel<<<(n4 + 255) / 256, 256>>>(x, xh, n4);
        n4 = (KDIM * N_IN) / 4;
        convert_h_kernel<<<(n4 + 255) / 256, 256>>>(W_in, wh_in, n4);
        n4 = (KDIM * D_MODEL) / 4;
        convert_h_kernel<<<(n4 + 255) / 256, 256>>>(W_out, wh_out, n4);
    }

    // GEMM1 (split epilogue): xc fp16 + zs=silu(z) fp16
    {
        dim3 grid(N_IN / BN, M_TOT / BM);
        gemm_fp16_kernel<true><<<grid, 256, GEMM_SMEM_BYTES>>>(
            xh, wh_in, nullptr, xcp, zsp, M_TOT, N_IN, KDIM);
    }
    // Fused single-pass scan (decoupled lookback)
    scan_fused_kernel<<<NVBLK, 192>>>(xcp, zsp, conv_w, conv_b,
                                      Bm, Cm, Dv, ag, pr, st, tk, yzh);
    // GEMM2: out = yzh @ W_out  [32768,768] x [768,768]
    {
        dim3 grid(D_MODEL / BN, M_TOT / BM);
        gemm_fp16_kernel<false><<<grid, 256, GEMM_SMEM_BYTES>>>(
            yzh, wh_out, out, nullptr, nullptr, M_TOT, D_MODEL, KDIM);
    }
}